// round 9
// baseline (speedup 1.0000x reference)
#include <cuda_runtime.h>
#include <cuda_bf16.h>

#define N_IN    11008
#define N_OUT   4096
#define TOPK_K  5504
#define N_CACHE 64
#define NBW     344            // ceil(11008/32)
#define TPB     256
#define GRID    512
#define NSYNC   128            // barrier group: blocks 0..127
#define CHUNK   43             // 256*43 == 11008 exactly

// ---- device-global scratch (allocation-free; fully rewritten each call) ----
__device__ __align__(16) float g_xm[N_IN];
__device__ unsigned g_maskbits[NBW];
__device__ int g_inter[N_CACHE];
__device__ unsigned g_barcnt;   // group barrier counter (monotonic, replay-safe)
__device__ unsigned g_arrive;   // per-launch arrival counter (monotonic)
__device__ unsigned g_done;     // xm-ready release counter (monotonic)

// Replay-safe barrier among blocks 0..NSYNC-1.
__device__ __forceinline__ void group_barrier() {
    __syncthreads();
    if (threadIdx.x == 0) {
        __threadfence();
        unsigned old = atomicAdd(&g_barcnt, 1u);
        unsigned target = (old / NSYNC + 1u) * NSYNC;
        unsigned cur;
        do {
            asm volatile("ld.acquire.gpu.u32 %0, [%1];"
                         : "=r"(cur) : "l"(&g_barcnt) : "memory");
        } while (cur < target);
    }
    __syncthreads();
}

// 256-thread block inclusive scan (one int per thread).
__device__ __forceinline__ int scan256(int v, int lane, int wid, int* sbuf) {
    __syncthreads();
    #pragma unroll
    for (int o = 1; o < 32; o <<= 1) {
        int t = __shfl_up_sync(0xffffffffu, v, o);
        if (lane >= o) v += t;
    }
    if (lane == 31) sbuf[wid] = v;
    __syncthreads();
    if (wid == 0) {
        int w = (lane < 8) ? sbuf[lane] : 0;
        #pragma unroll
        for (int o = 1; o < 8; o <<= 1) {
            int t = __shfl_up_sync(0xffffffffu, w, o);
            if (lane >= o) w += t;
        }
        if (lane < 8) sbuf[lane] = w;
    }
    __syncthreads();
    if (wid > 0) v += sbuf[wid - 1];
    return v;
}

// ============================================================================
// Mega-kernel, one launch:
//   block 0:        smem-resident radix-256 top-K select -> g_maskbits
//   blocks 64..127: cache bitsets -> intersection -> g_inter  (overlaps select)
//   blocks 0..42:   xm build after decision
//   blocks 128..511: sleep-poll release, then GEMV (with everyone else)
// ============================================================================
__global__ void __launch_bounds__(TPB, 4)
mega_kernel(const float* __restrict__ x, const int* __restrict__ cached,
            const float* __restrict__ W, const float* __restrict__ bias,
            float* __restrict__ out) {
    __shared__ unsigned s_mem[N_IN];     // block 0: |x| bits; blocks 64-127: cbits
    __shared__ unsigned s_hist[256];
    __shared__ unsigned s_bits[NBW];
    __shared__ int sbuf[8];
    __shared__ int s_d, s_excl, s_use, s_best;
    __shared__ unsigned s_gen;

    const int b = blockIdx.x, tid = threadIdx.x;
    const int lane = tid & 31, wid = tid >> 5;

    if (tid == 0) s_gen = atomicAdd(&g_arrive, 1u) / GRID;   // launch generation
    __syncthreads();

    if (b < NSYNC) {
        // ---------------- pre-work group ----------------
        if (b == 0) {
            // load |x| bit patterns into smem (coalesced)
            for (int i = tid; i < N_IN; i += TPB)
                s_mem[i] = __float_as_uint(x[i]) & 0x7FFFFFFFu;
            __syncthreads();

            // 4-level radix-256 select, entirely in smem
            unsigned prefix = 0;
            int Kr = TOPK_K;
            for (int l = 0; l < 4; l++) {
                const int shift = 24 - 8 * l;
                s_hist[tid] = 0;
                __syncthreads();
                for (int k = 0; k < CHUNK; k++) {
                    unsigned u = s_mem[tid * CHUNK + k];
                    bool in_class = (l == 0) || ((u >> (shift + 8)) == prefix);
                    if (in_class) atomicAdd(&s_hist[(u >> shift) & 255], 1u);
                }
                __syncthreads();
                const int j = 255 - tid;
                const int h = (int)s_hist[j];
                int S = scan256(h, lane, wid, sbuf);   // count(dig >= j) in class
                int excl = S - h;                      // count(dig >  j)
                if (S >= Kr && excl < Kr) { s_d = j; s_excl = excl; }
                __syncthreads();
                Kr -= s_excl;
                prefix = (prefix << 8) | (unsigned)s_d;
                __syncthreads();
            }
            const unsigned T = prefix;                 // threshold value bits
            const int need = Kr;                       // ties to take

            // tie rank (index-ascending) + mask build
            for (int i = tid; i < NBW; i += TPB) s_bits[i] = 0;
            int tieCnt = 0;
            for (int k = 0; k < CHUNK; k++)
                if (s_mem[tid * CHUNK + k] == T) tieCnt++;
            int incl = scan256(tieCnt, lane, wid, sbuf);
            int rank = incl - tieCnt;
            for (int k = 0; k < CHUNK; k++) {
                const int i = tid * CHUNK + k;
                unsigned u = s_mem[i];
                bool sel;
                if (u > T)       sel = true;
                else if (u == T) { sel = (rank < need); rank++; }
                else             sel = false;
                if (sel) atomicOr(&s_bits[i >> 5], 1u << (i & 31));
            }
            __syncthreads();
            for (int i = tid; i < NBW; i += TPB) g_maskbits[i] = s_bits[i];
        } else if (b >= 64) {
            // cache bitset for cache (b-64), concurrent with block-0 select
            for (int i = tid; i < NBW; i += TPB) s_mem[i] = 0;
            __syncthreads();
            const int* row = cached + (b - 64) * TOPK_K;
            for (int k = tid; k < TOPK_K; k += TPB) {
                int idx = row[k];
                atomicOr(&s_mem[idx >> 5], 1u << (idx & 31));
            }
            __syncthreads();
        }

        group_barrier();   // B1: maskbits + cbits ready

        // intersection (deduped) by blocks 64..127
        if (b >= 64) {
            int cnt = 0;
            for (int i = tid; i < NBW; i += TPB)
                cnt += __popc(s_mem[i] & g_maskbits[i]);
            #pragma unroll
            for (int o = 16; o; o >>= 1) cnt += __shfl_down_sync(0xffffffffu, cnt, o);
            __syncthreads();
            if (lane == 0) sbuf[wid] = cnt;
            __syncthreads();
            if (tid == 0) {
                int s = 0;
                #pragma unroll
                for (int i = 0; i < 8; i++) s += sbuf[i];
                g_inter[b - 64] = s;
            }
        }

        group_barrier();   // B2: g_inter ready

        // decision (redundant per group block; uniform result)
        if (tid == 0) {
            float best = -1.0f; int bi = 0;
            #pragma unroll
            for (int i = 0; i < N_CACHE; i++) {
                float r = (float)g_inter[i] / (float)TOPK_K;
                if (r > best) { best = r; bi = i; }   // first-max = argmax
            }
            s_use  = (best >= 0.9f) ? 1 : 0;
            s_best = bi;
        }
        __syncthreads();

        // xm base build by blocks 0..42 (43*256 == N_IN)
        if (b < 43) {
            const int gi = b * TPB + tid;
            if (!s_use) {
                int sel = (g_maskbits[gi >> 5] >> (gi & 31)) & 1;
                g_xm[gi] = sel ? x[gi] : 0.0f;
            } else {
                g_xm[gi] = 0.0f;
            }
        }

        group_barrier();   // B3: xm base done

        // cache-path scatter by blocks 0..21 (22*256 >= TOPK_K)
        if (s_use && b < 22) {
            const int k = b * TPB + tid;
            if (k < TOPK_K) {
                int idx = cached[s_best * TOPK_K + k];
                atomicAdd(&g_xm[idx], x[idx]);   // duplicates = multiplicity
            }
        }

        group_barrier();   // B4: xm final

        if (b == 0 && tid == 0) {
            __threadfence();
            atomicAdd(&g_done, 1u);              // release to non-group blocks
        }
    } else {
        // ---------------- non-group blocks: wait for xm ----------------
        if (tid == 0) {
            const unsigned target = s_gen + 1u;
            unsigned cur;
            for (;;) {
                asm volatile("ld.acquire.gpu.u32 %0, [%1];"
                             : "=r"(cur) : "l"(&g_done) : "memory");
                if (cur >= target) break;
                __nanosleep(256);
            }
        }
        __syncthreads();
    }

    // ---- GEMV (exact R4 pattern: 1 row/warp, 4096 streams @ 5.3 TB/s) ----
    const int row = b * 8 + wid;                 // 0..4095
    const float4* __restrict__ w4 = (const float4*)(W + (long long)row * N_IN);
    const float4* __restrict__ x4 = (const float4*)g_xm;

    float a0 = 0.0f, a1 = 0.0f;
    #pragma unroll 4
    for (int it = 0; it < 43; it++) {
        const int j = lane + it * 64;
        float4 w  = __ldcs(w4 + j);
        float4 v  = x4[j];
        a0 += w.x * v.x + w.y * v.y;
        a1 += w.z * v.z + w.w * v.w;
        float4 w2 = __ldcs(w4 + j + 32);
        float4 v2 = x4[j + 32];
        a0 += w2.x * v2.x + w2.y * v2.y;
        a1 += w2.z * v2.z + w2.w * v2.w;
    }
    float acc = a0 + a1;
    #pragma unroll
    for (int o = 16; o; o >>= 1) acc += __shfl_down_sync(0xffffffffu, acc, o);
    if (lane == 0) out[row] = acc + bias[row];
}

// ============================================================================
extern "C" void kernel_launch(void* const* d_in, const int* in_sizes, int n_in,
                              void* d_out, int out_size) {
    const float* x      = (const float*)d_in[0];
    const float* W      = (const float*)d_in[1];
    const float* bias   = (const float*)d_in[2];
    const int*   cached = (const int*)d_in[3];
    float*       out    = (float*)d_out;

    mega_kernel<<<GRID, TPB>>>(x, cached, W, bias, out);
}

// round 10
// speedup vs baseline: 1.1045x; 1.1045x over previous
#include <cuda_runtime.h>
#include <cuda_bf16.h>

#define N_IN    11008
#define N_OUT   4096
#define TOPK_K  5504
#define N_CACHE 64
#define NBW     344            // ceil(11008/32)
#define TPB     512
#define GRID    256            // 256 blocks x 16 warps = 4096 warps = 1 row/warp
#define NSYNC   65             // barrier group: block 0 (select) + 1..64 (caches)
#define CHUNK   22             // per-thread contiguous slice in select (512*22>=11008)

// ---- device-global scratch (allocation-free; fully rewritten each call) ----
__device__ __align__(16) float g_xm[N_IN];
__device__ unsigned g_maskbits[NBW];
__device__ int g_inter[N_CACHE];
__device__ unsigned g_barcnt;   // group barrier counter (monotonic, replay-safe)
__device__ unsigned g_arrive;   // launch arrival counter (monotonic)
__device__ unsigned g_done;     // xm-ready release counter (monotonic)

// Replay-safe barrier among blocks 0..NSYNC-1, gentle polling.
__device__ __forceinline__ void group_barrier() {
    __syncthreads();
    if (threadIdx.x == 0) {
        __threadfence();
        unsigned old = atomicAdd(&g_barcnt, 1u);
        unsigned target = (old / NSYNC + 1u) * NSYNC;
        unsigned cur;
        for (;;) {
            asm volatile("ld.acquire.gpu.u32 %0, [%1];"
                         : "=r"(cur) : "l"(&g_barcnt) : "memory");
            if (cur >= target) break;
            __nanosleep(64);
        }
    }
    __syncthreads();
}

// 512-thread block inclusive scan (one int per thread).
__device__ __forceinline__ int scan512(int v, int lane, int wid, int* sbuf) {
    __syncthreads();
    #pragma unroll
    for (int o = 1; o < 32; o <<= 1) {
        int t = __shfl_up_sync(0xffffffffu, v, o);
        if (lane >= o) v += t;
    }
    if (lane == 31) sbuf[wid] = v;
    __syncthreads();
    if (wid == 0) {
        int w = (lane < 16) ? sbuf[lane] : 0;
        #pragma unroll
        for (int o = 1; o < 16; o <<= 1) {
            int t = __shfl_up_sync(0xffffffffu, w, o);
            if (lane >= o) w += t;
        }
        if (lane < 16) sbuf[lane] = w;
    }
    __syncthreads();
    if (wid > 0) v += sbuf[wid - 1];
    return v;
}

// ============================================================================
// Mega-kernel, ONE launch:
//   block 0:      smem-staged radix-256 top-K select -> g_maskbits
//   blocks 1..64: cache bitset (concurrent w/ select) -> intersection
//   blocks 0..21: xm build after decision;  release via g_done
//   blocks 65..255: sleep-poll release;  ALL blocks: GEMV (1 row/warp)
// ============================================================================
__global__ void __launch_bounds__(TPB, 2)
mega_kernel(const float* __restrict__ x, const int* __restrict__ cached,
            const float* __restrict__ W, const float* __restrict__ bias,
            float* __restrict__ out) {
    __shared__ unsigned s_mem[N_IN];     // block 0: |x| bits; blocks 1-64: cbits
    __shared__ unsigned s_hist[256];
    __shared__ unsigned s_bits[NBW];
    __shared__ int sbuf[16];
    __shared__ int s_d, s_excl, s_use, s_best;
    __shared__ unsigned s_gen;

    const int b = blockIdx.x, tid = threadIdx.x;
    const int lane = tid & 31, wid = tid >> 5;

    if (tid == 0) s_gen = atomicAdd(&g_arrive, 1u) / GRID;   // launch generation
    __syncthreads();

    if (b < NSYNC) {
        if (b == 0) {
            // ---- stage |x| bits in smem (coalesced) ----
            for (int i = tid; i < N_IN; i += TPB)
                s_mem[i] = __float_as_uint(x[i]) & 0x7FFFFFFFu;
            __syncthreads();

            // ---- 4-level radix-256 select, smem-resident ----
            const int start = tid * CHUNK;
            const int end   = min(start + CHUNK, N_IN);
            unsigned prefix = 0;
            int Kr = TOPK_K;
            for (int l = 0; l < 4; l++) {
                const int shift = 24 - 8 * l;
                if (tid < 256) s_hist[tid] = 0;
                __syncthreads();
                for (int i = start; i < end; i++) {
                    unsigned u = s_mem[i];
                    bool in_class = (l == 0) || ((u >> (shift + 8)) == prefix);
                    if (in_class) atomicAdd(&s_hist[(u >> shift) & 255], 1u);
                }
                __syncthreads();
                const int h = (tid < 256) ? (int)s_hist[255 - tid] : 0;
                int S = scan512(h, lane, wid, sbuf);   // count(dig >= j) in class
                int excl = S - h;                      // count(dig >  j)
                if (tid < 256 && S >= Kr && excl < Kr) { s_d = 255 - tid; s_excl = excl; }
                __syncthreads();
                Kr -= s_excl;
                prefix = (prefix << 8) | (unsigned)s_d;
                __syncthreads();
            }
            const unsigned T = prefix;                 // threshold bits
            const int need = Kr;                       // ties to take

            // ---- tie rank (index-ascending) + mask build ----
            for (int i = tid; i < NBW; i += TPB) s_bits[i] = 0;
            int tieCnt = 0;
            for (int i = start; i < end; i++)
                if (s_mem[i] == T) tieCnt++;
            int incl = scan512(tieCnt, lane, wid, sbuf);
            int rank = incl - tieCnt;
            for (int i = start; i < end; i++) {
                unsigned u = s_mem[i];
                bool sel;
                if (u > T)       sel = true;
                else if (u == T) { sel = (rank < need); rank++; }
                else             sel = false;
                if (sel) atomicOr(&s_bits[i >> 5], 1u << (i & 31));
            }
            __syncthreads();
            for (int i = tid; i < NBW; i += TPB) g_maskbits[i] = s_bits[i];
        } else {
            // ---- cache bitset for cache (b-1), concurrent with select ----
            for (int i = tid; i < NBW; i += TPB) s_mem[i] = 0;
            __syncthreads();
            const int* row = cached + (b - 1) * TOPK_K;
            for (int k = tid; k < TOPK_K; k += TPB) {
                int idx = row[k];
                atomicOr(&s_mem[idx >> 5], 1u << (idx & 31));
            }
            __syncthreads();
        }

        group_barrier();   // B1: maskbits + cbits ready

        // ---- deduped intersection by blocks 1..64 ----
        if (b >= 1) {
            int cnt = 0;
            for (int i = tid; i < NBW; i += TPB)
                cnt += __popc(s_mem[i] & g_maskbits[i]);
            #pragma unroll
            for (int o = 16; o; o >>= 1) cnt += __shfl_down_sync(0xffffffffu, cnt, o);
            __syncthreads();
            if (lane == 0) sbuf[wid] = cnt;
            __syncthreads();
            if (tid == 0) {
                int s = 0;
                #pragma unroll
                for (int i = 0; i < 16; i++) s += sbuf[i];
                g_inter[b - 1] = s;
            }
        }

        group_barrier();   // B2: g_inter ready

        // ---- decision (redundant per group block; uniform) ----
        if (tid == 0) {
            float best = -1.0f; int bi = 0;
            #pragma unroll
            for (int i = 0; i < N_CACHE; i++) {
                float r = (float)g_inter[i] / (float)TOPK_K;
                if (r > best) { best = r; bi = i; }   // first-max = argmax
            }
            s_use  = (best >= 0.9f) ? 1 : 0;
            s_best = bi;
        }
        __syncthreads();

        // ---- xm base by blocks 0..21 (22*512 >= N_IN) ----
        if (b < 22) {
            const int gi = b * TPB + tid;
            if (gi < N_IN) {
                if (!s_use) {
                    int sel = (g_maskbits[gi >> 5] >> (gi & 31)) & 1;
                    g_xm[gi] = sel ? x[gi] : 0.0f;
                } else {
                    g_xm[gi] = 0.0f;
                }
            }
        }

        group_barrier();   // B3: xm base done

        // ---- cache-path scatter by blocks 0..10 (11*512 >= TOPK_K) ----
        if (s_use && b < 11) {
            const int k = b * TPB + tid;
            if (k < TOPK_K) {
                int idx = cached[s_best * TOPK_K + k];
                atomicAdd(&g_xm[idx], x[idx]);   // duplicates = multiplicity
            }
        }

        group_barrier();   // B4: xm final

        if (b == 0 && tid == 0) {
            __threadfence();
            atomicAdd(&g_done, 1u);              // release
        }
    } else {
        // ---- non-group blocks: sleep-poll until xm ready ----
        if (tid == 0) {
            const unsigned target = s_gen + 1u;
            unsigned cur;
            for (;;) {
                asm volatile("ld.acquire.gpu.u32 %0, [%1];"
                             : "=r"(cur) : "l"(&g_done) : "memory");
                if (cur >= target) break;
                __nanosleep(128);
            }
        }
        __syncthreads();
    }

    // ---- GEMV: exact R4 pattern — 1 row/warp, 4096 x 44KB streams ----
    const int row = b * 16 + wid;                // 0..4095
    const float4* __restrict__ w4 = (const float4*)(W + (long long)row * N_IN);
    const float4* __restrict__ x4 = (const float4*)g_xm;

    float a0 = 0.0f, a1 = 0.0f;
    #pragma unroll 4
    for (int it = 0; it < 43; it++) {
        const int j = lane + it * 64;
        float4 w  = __ldcs(w4 + j);
        float4 v  = x4[j];
        a0 += w.x * v.x + w.y * v.y;
        a1 += w.z * v.z + w.w * v.w;
        float4 w2 = __ldcs(w4 + j + 32);
        float4 v2 = x4[j + 32];
        a0 += w2.x * v2.x + w2.y * v2.y;
        a1 += w2.z * v2.z + w2.w * v2.w;
    }
    float acc = a0 + a1;
    #pragma unroll
    for (int o = 16; o; o >>= 1) acc += __shfl_down_sync(0xffffffffu, acc, o);
    if (lane == 0) out[row] = acc + bias[row];
}

// ============================================================================
extern "C" void kernel_launch(void* const* d_in, const int* in_sizes, int n_in,
                              void* d_out, int out_size) {
    const float* x      = (const float*)d_in[0];
    const float* W      = (const float*)d_in[1];
    const float* bias   = (const float*)d_in[2];
    const int*   cached = (const int*)d_in[3];
    float*       out    = (float*)d_out;

    mega_kernel<<<GRID, TPB>>>(x, cached, W, bias, out);
}

// round 11
// speedup vs baseline: 1.2876x; 1.1657x over previous
#include <cuda_runtime.h>
#include <cuda_bf16.h>

#define N_IN    11008
#define N_OUT   4096
#define TOPK_K  5504
#define N_CACHE 64
#define NBW     344            // ceil(11008/32)
#define TPB     1024
#define GRID    128            // 128 blocks x 32 warps = 4096 warps = 1 row/warp
#define NSYNC   65             // barrier group: block 0 (select) + 1..64 (caches)

// ---- device-global scratch (allocation-free; fully rewritten each call) ----
__device__ __align__(16) float g_xm[N_IN];
__device__ unsigned g_maskbits[NBW];
__device__ int g_inter[N_CACHE];
__device__ unsigned g_barcnt;   // group barrier counter (monotonic, replay-safe)
__device__ unsigned g_arrive;   // launch arrival counter (monotonic)
__device__ unsigned g_done;     // xm-ready release counter (monotonic)

// Replay-safe barrier among blocks 0..NSYNC-1, gentle polling.
__device__ __forceinline__ void group_barrier() {
    __syncthreads();
    if (threadIdx.x == 0) {
        __threadfence();
        unsigned old = atomicAdd(&g_barcnt, 1u);
        unsigned target = (old / NSYNC + 1u) * NSYNC;
        unsigned cur;
        for (;;) {
            asm volatile("ld.acquire.gpu.u32 %0, [%1];"
                         : "=r"(cur) : "l"(&g_barcnt) : "memory");
            if (cur >= target) break;
            __nanosleep(64);
        }
    }
    __syncthreads();
}

// 1024-thread block inclusive scan (one int per thread).
__device__ __forceinline__ int scan1024(int v, int lane, int wid, int* sbuf) {
    __syncthreads();
    #pragma unroll
    for (int o = 1; o < 32; o <<= 1) {
        int t = __shfl_up_sync(0xffffffffu, v, o);
        if (lane >= o) v += t;
    }
    if (lane == 31) sbuf[wid] = v;
    __syncthreads();
    if (wid == 0) {
        int w = sbuf[lane];
        #pragma unroll
        for (int o = 1; o < 32; o <<= 1) {
            int t = __shfl_up_sync(0xffffffffu, w, o);
            if (lane >= o) w += t;
        }
        sbuf[lane] = w;
    }
    __syncthreads();
    if (wid > 0) v += sbuf[wid - 1];
    return v;
}

// ============================================================================
// Mega-kernel, ONE launch, 128 blocks x 1024 threads:
//   block 0:       smem-staged 3-level radix select (1024 thr) -> g_maskbits
//   blocks 1..64:  cache bitsets (concurrent w/ select) -> intersection
//   blocks 0..10:  xm build after decision; block 0 releases g_done
//   blocks 65..127: sleep-poll release;  ALL blocks: GEMV (1 row/warp)
// ============================================================================
__global__ void __launch_bounds__(TPB, 1)
mega_kernel(const float* __restrict__ x, const int* __restrict__ cached,
            const float* __restrict__ W, const float* __restrict__ bias,
            float* __restrict__ out) {
    __shared__ unsigned s_mem[N_IN];     // block 0: |x| bits; blocks 1-64: cbits
    __shared__ unsigned hist[2048];
    __shared__ unsigned s_bits[NBW];
    __shared__ int scanbuf[32];
    __shared__ int s_b, s_G, s_need, s_use, s_best;
    __shared__ unsigned s_T, s_gen;

    const int b = blockIdx.x, tid = threadIdx.x;
    const int lane = tid & 31, wid = tid >> 5;

    if (tid == 0) s_gen = atomicAdd(&g_arrive, 1u) / GRID;   // launch generation
    __syncthreads();

    if (b < NSYNC) {
        if (b == 0) {
            // ---- stage |x| bit patterns in smem (coalesced, one global pass) ----
            for (int i = tid; i < N_IN; i += TPB)
                s_mem[i] = __float_as_uint(x[i]) & 0x7FFFFFFFu;
            for (int i = tid; i < NBW; i += TPB) s_bits[i] = 0;
            __syncthreads();

            // ---- level 0: bits [30:21] (1024 bins used) ----
            for (int i = tid; i < 2048; i += TPB) hist[i] = 0;
            __syncthreads();
            for (int i = tid; i < N_IN; i += TPB)
                atomicAdd(&hist[s_mem[i] >> 21], 1u);
            __syncthreads();
            {
                const int j0 = 2047 - 2 * tid, j1 = j0 - 1;
                const int h0 = hist[j0], h1 = hist[j1];
                int S = scan1024(h0 + h1, lane, wid, scanbuf);
                int excl = S - h0 - h1;
                const int Kr = TOPK_K;
                if (excl + h0 >= Kr && excl < Kr)   { s_b = j0; s_G = excl; }
                else if (S >= Kr && excl + h0 < Kr) { s_b = j1; s_G = excl + h0; }
            }
            __syncthreads();
            const int b0 = s_b, G0 = s_G;

            // ---- level 1: bits [20:10] ----
            __syncthreads();
            for (int i = tid; i < 2048; i += TPB) hist[i] = 0;
            __syncthreads();
            for (int i = tid; i < N_IN; i += TPB) {
                unsigned u = s_mem[i];
                if ((int)(u >> 21) == b0) atomicAdd(&hist[(u >> 10) & 0x7FF], 1u);
            }
            __syncthreads();
            {
                const int j0 = 2047 - 2 * tid, j1 = j0 - 1;
                const int h0 = hist[j0], h1 = hist[j1];
                int S = scan1024(h0 + h1, lane, wid, scanbuf);
                int excl = S - h0 - h1;
                const int Kr = TOPK_K - G0;
                if (excl + h0 >= Kr && excl < Kr)   { s_b = j0; s_G = G0 + excl; }
                else if (S >= Kr && excl + h0 < Kr) { s_b = j1; s_G = G0 + excl + h0; }
            }
            __syncthreads();
            const int b1 = s_b, G1 = s_G;

            // ---- level 2: bits [9:0] ----
            __syncthreads();
            for (int i = tid; i < 2048; i += TPB) hist[i] = 0;
            __syncthreads();
            const unsigned top22 = ((unsigned)b0 << 21) | ((unsigned)b1 << 10);
            for (int i = tid; i < N_IN; i += TPB) {
                unsigned u = s_mem[i];
                if ((u & 0xFFFFFC00u) == top22) atomicAdd(&hist[u & 0x3FF], 1u);
            }
            __syncthreads();
            {
                const int j = 1023 - tid;
                const int h = (tid < 1024) ? (int)hist[j] : 0;
                int S = scan1024(h, lane, wid, scanbuf);
                int excl = S - h;
                const int Kr = TOPK_K - G1;
                if (S >= Kr && excl < Kr) { s_T = top22 | (unsigned)j; s_need = Kr - excl; }
            }
            __syncthreads();
            const unsigned T = s_T;
            const int need = s_need;

            // ---- mask build with smallest-index tie-break ----
            const int CHUNK = (N_IN + TPB - 1) / TPB;   // 11
            const int start = tid * CHUNK;
            const int end   = min(start + CHUNK, N_IN);

            int tieCnt = 0;
            for (int i = start; i < end; i++)
                if (s_mem[i] == T) tieCnt++;
            int incl = scan1024(tieCnt, lane, wid, scanbuf);
            int rank = incl - tieCnt;

            for (int i = start; i < end; i++) {
                unsigned u = s_mem[i];
                bool sel;
                if (u > T)       sel = true;
                else if (u == T) { sel = (rank < need); rank++; }
                else             sel = false;
                if (sel) atomicOr(&s_bits[i >> 5], 1u << (i & 31));
            }
            __syncthreads();
            for (int i = tid; i < NBW; i += TPB) g_maskbits[i] = s_bits[i];
        } else {
            // ---- cache bitset for cache (b-1), concurrent with select ----
            for (int i = tid; i < NBW; i += TPB) s_mem[i] = 0;
            __syncthreads();
            const int* row = cached + (b - 1) * TOPK_K;
            for (int k = tid; k < TOPK_K; k += TPB) {
                int idx = row[k];
                atomicOr(&s_mem[idx >> 5], 1u << (idx & 31));
            }
            __syncthreads();
        }

        group_barrier();   // B1: maskbits + cbits ready

        // ---- deduped intersection by blocks 1..64 ----
        if (b >= 1) {
            int cnt = 0;
            for (int i = tid; i < NBW; i += TPB)
                cnt += __popc(s_mem[i] & g_maskbits[i]);
            #pragma unroll
            for (int o = 16; o; o >>= 1) cnt += __shfl_down_sync(0xffffffffu, cnt, o);
            __syncthreads();
            if (lane == 0) scanbuf[wid] = cnt;
            __syncthreads();
            if (tid == 0) {
                int s = 0;
                #pragma unroll
                for (int i = 0; i < 32; i++) s += scanbuf[i];
                g_inter[b - 1] = s;
            }
        }

        group_barrier();   // B2: g_inter ready

        // ---- decision (redundant per group block; uniform) ----
        if (tid == 0) {
            float best = -1.0f; int bi = 0;
            #pragma unroll
            for (int i = 0; i < N_CACHE; i++) {
                float r = (float)g_inter[i] / (float)TOPK_K;
                if (r > best) { best = r; bi = i; }   // first-max = argmax
            }
            s_use  = (best >= 0.9f) ? 1 : 0;
            s_best = bi;
        }
        __syncthreads();

        // ---- xm base by blocks 0..10 (11*1024 >= N_IN) ----
        if (b < 11) {
            const int gi = b * TPB + tid;
            if (gi < N_IN) {
                if (!s_use) {
                    int sel = (g_maskbits[gi >> 5] >> (gi & 31)) & 1;
                    g_xm[gi] = sel ? x[gi] : 0.0f;
                } else {
                    g_xm[gi] = 0.0f;
                }
            }
        }

        group_barrier();   // B3: xm base done

        // ---- cache-path scatter by blocks 0..5 (6*1024 >= TOPK_K) ----
        if (s_use && b < 6) {
            const int k = b * TPB + tid;
            if (k < TOPK_K) {
                int idx = cached[s_best * TOPK_K + k];
                atomicAdd(&g_xm[idx], x[idx]);   // duplicates = multiplicity
            }
        }

        group_barrier();   // B4: xm final

        if (b == 0 && tid == 0) {
            __threadfence();
            atomicAdd(&g_done, 1u);              // release
        }
    } else {
        // ---- non-group blocks: sleep-poll until xm ready ----
        if (tid == 0) {
            const unsigned target = s_gen + 1u;
            unsigned cur;
            for (;;) {
                asm volatile("ld.acquire.gpu.u32 %0, [%1];"
                             : "=r"(cur) : "l"(&g_done) : "memory");
                if (cur >= target) break;
                __nanosleep(128);
            }
        }
        __syncthreads();
    }

    // ---- GEMV: exact R4 pattern — 1 row/warp, 4096 x 44KB streams ----
    const int row = b * 32 + wid;                // 0..4095
    const float4* __restrict__ w4 = (const float4*)(W + (long long)row * N_IN);
    const float4* __restrict__ x4 = (const float4*)g_xm;

    float a0 = 0.0f, a1 = 0.0f;
    #pragma unroll 4
    for (int it = 0; it < 43; it++) {
        const int j = lane + it * 64;
        float4 w  = __ldcs(w4 + j);
        float4 v  = x4[j];
        a0 += w.x * v.x + w.y * v.y;
        a1 += w.z * v.z + w.w * v.w;
        float4 w2 = __ldcs(w4 + j + 32);
        float4 v2 = x4[j + 32];
        a0 += w2.x * v2.x + w2.y * v2.y;
        a1 += w2.z * v2.z + w2.w * v2.w;
    }
    float acc = a0 + a1;
    #pragma unroll
    for (int o = 16; o; o >>= 1) acc += __shfl_down_sync(0xffffffffu, acc, o);
    if (lane == 0) out[row] = acc + bias[row];
}

// ============================================================================
extern "C" void kernel_launch(void* const* d_in, const int* in_sizes, int n_in,
                              void* d_out, int out_size) {
    const float* x      = (const float*)d_in[0];
    const float* W      = (const float*)d_in[1];
    const float* bias   = (const float*)d_in[2];
    const int*   cached = (const int*)d_in[3];
    float*       out    = (float*)d_out;

    mega_kernel<<<GRID, TPB>>>(x, cached, W, bias, out);
}

// round 12
// speedup vs baseline: 1.3421x; 1.0423x over previous
#include <cuda_runtime.h>
#include <cuda_bf16.h>

#define N_IN    11008
#define N_OUT   4096
#define TOPK_K  5504
#define N_CACHE 64
#define NBW     344            // ceil(11008/32)
#define TPB     1024
#define GRID    128            // 128 blocks x 32 warps = 4096 warps = 1 row/warp

// ---- device-global scratch (allocation-free; fully rewritten each call) ----
__device__ __align__(16) float g_xm[N_IN];
__device__ unsigned g_maskbits[NBW];
__device__ int g_inter[N_CACHE];
__device__ unsigned g_arrive;     // launch arrival counter (monotonic)
__device__ unsigned g_mask_done;  // +1 per launch when maskbits published
__device__ unsigned g_int_done;   // +64 per launch when intersections written
__device__ unsigned g_xm_done;    // +11 per launch when xm final

// Sleep-poll until *addr >= target (acquire).
__device__ __forceinline__ void poll_ge(const unsigned* addr, unsigned target) {
    unsigned cur;
    for (;;) {
        asm volatile("ld.acquire.gpu.u32 %0, [%1];"
                     : "=r"(cur) : "l"(addr) : "memory");
        if (cur >= target) break;
        __nanosleep(64);
    }
}

// 1024-thread block inclusive scan (one int per thread).
__device__ __forceinline__ int scan1024(int v, int lane, int wid, int* sbuf) {
    __syncthreads();
    #pragma unroll
    for (int o = 1; o < 32; o <<= 1) {
        int t = __shfl_up_sync(0xffffffffu, v, o);
        if (lane >= o) v += t;
    }
    if (lane == 31) sbuf[wid] = v;
    __syncthreads();
    if (wid == 0) {
        int w = sbuf[lane];
        #pragma unroll
        for (int o = 1; o < 32; o <<= 1) {
            int t = __shfl_up_sync(0xffffffffu, w, o);
            if (lane >= o) w += t;
        }
        sbuf[lane] = w;
    }
    __syncthreads();
    if (wid > 0) v += sbuf[wid - 1];
    return v;
}

// ============================================================================
// Mega-kernel, ONE launch, 128 blocks x 1024 threads, counter-released phases:
//   block 0:      smem radix select -> maskbits -> g_mask_done++
//   blocks 1..64: cbits (concurrent) -> poll mask -> intersection -> g_int_done++
//   blocks 0..10: poll int==64 -> decision -> xm chunk -> g_xm_done += 1 (or 11)
//   everyone:     poll xm==11 -> GEMV (1 row/warp, proven 5.3 TB/s pattern)
// ============================================================================
__global__ void __launch_bounds__(TPB, 1)
mega_kernel(const float* __restrict__ x, const int* __restrict__ cached,
            const float* __restrict__ W, const float* __restrict__ bias,
            float* __restrict__ out) {
    __shared__ unsigned s_mem[N_IN];     // block 0: |x| bits; blocks 1-64: cbits
    __shared__ unsigned hist[2048];
    __shared__ unsigned s_bits[NBW];
    __shared__ int scanbuf[32];
    __shared__ int s_b, s_G, s_need, s_use, s_best;
    __shared__ unsigned s_T, s_gen;

    const int b = blockIdx.x, tid = threadIdx.x;
    const int lane = tid & 31, wid = tid >> 5;

    if (tid == 0) s_gen = atomicAdd(&g_arrive, 1u) / GRID;   // launch generation
    __syncthreads();
    const unsigned gen = s_gen;

    if (b == 0) {
        // ---- fused stage + level-0 histogram (bits [30:21]) ----
        for (int i = tid; i < 2048; i += TPB) hist[i] = 0;
        for (int i = tid; i < NBW; i += TPB) s_bits[i] = 0;
        __syncthreads();
        for (int i = tid; i < N_IN; i += TPB) {
            unsigned u = __float_as_uint(x[i]) & 0x7FFFFFFFu;
            s_mem[i] = u;
            atomicAdd(&hist[u >> 21], 1u);
        }
        __syncthreads();
        {
            const int j0 = 2047 - 2 * tid, j1 = j0 - 1;
            const int h0 = hist[j0], h1 = hist[j1];
            int S = scan1024(h0 + h1, lane, wid, scanbuf);
            int excl = S - h0 - h1;
            const int Kr = TOPK_K;
            if (excl + h0 >= Kr && excl < Kr)   { s_b = j0; s_G = excl; }
            else if (S >= Kr && excl + h0 < Kr) { s_b = j1; s_G = excl + h0; }
        }
        __syncthreads();
        const int b0 = s_b, G0 = s_G;

        // ---- level 1: bits [20:10] ----
        __syncthreads();
        for (int i = tid; i < 2048; i += TPB) hist[i] = 0;
        __syncthreads();
        for (int i = tid; i < N_IN; i += TPB) {
            unsigned u = s_mem[i];
            if ((int)(u >> 21) == b0) atomicAdd(&hist[(u >> 10) & 0x7FF], 1u);
        }
        __syncthreads();
        {
            const int j0 = 2047 - 2 * tid, j1 = j0 - 1;
            const int h0 = hist[j0], h1 = hist[j1];
            int S = scan1024(h0 + h1, lane, wid, scanbuf);
            int excl = S - h0 - h1;
            const int Kr = TOPK_K - G0;
            if (excl + h0 >= Kr && excl < Kr)   { s_b = j0; s_G = G0 + excl; }
            else if (S >= Kr && excl + h0 < Kr) { s_b = j1; s_G = G0 + excl + h0; }
        }
        __syncthreads();
        const int b1 = s_b, G1 = s_G;

        // ---- level 2: bits [9:0] ----
        __syncthreads();
        for (int i = tid; i < 2048; i += TPB) hist[i] = 0;
        __syncthreads();
        const unsigned top22 = ((unsigned)b0 << 21) | ((unsigned)b1 << 10);
        for (int i = tid; i < N_IN; i += TPB) {
            unsigned u = s_mem[i];
            if ((u & 0xFFFFFC00u) == top22) atomicAdd(&hist[u & 0x3FF], 1u);
        }
        __syncthreads();
        {
            const int j = 1023 - tid;
            const int h = (int)hist[j];
            int S = scan1024(h, lane, wid, scanbuf);
            int excl = S - h;
            const int Kr = TOPK_K - G1;
            if (S >= Kr && excl < Kr) { s_T = top22 | (unsigned)j; s_need = Kr - excl; }
        }
        __syncthreads();
        const unsigned T = s_T;
        const int need = s_need;

        // ---- mask build with smallest-index tie-break ----
        const int CHUNK = (N_IN + TPB - 1) / TPB;   // 11
        const int start = tid * CHUNK;
        const int end   = min(start + CHUNK, N_IN);

        int tieCnt = 0;
        for (int i = start; i < end; i++)
            if (s_mem[i] == T) tieCnt++;
        int incl = scan1024(tieCnt, lane, wid, scanbuf);
        int rank = incl - tieCnt;

        for (int i = start; i < end; i++) {
            unsigned u = s_mem[i];
            bool sel;
            if (u > T)       sel = true;
            else if (u == T) { sel = (rank < need); rank++; }
            else             sel = false;
            if (sel) atomicOr(&s_bits[i >> 5], 1u << (i & 31));
        }
        __syncthreads();
        for (int i = tid; i < NBW; i += TPB) g_maskbits[i] = s_bits[i];
        __syncthreads();
        if (tid == 0) {
            __threadfence();
            atomicAdd(&g_mask_done, 1u);            // release maskbits
        }
    } else if (b <= 64) {
        // ---- cache bitset for cache (b-1), fully concurrent with select ----
        for (int i = tid; i < NBW; i += TPB) s_mem[i] = 0;
        __syncthreads();
        const int* row = cached + (b - 1) * TOPK_K;
        for (int k = tid; k < TOPK_K; k += TPB) {
            int idx = row[k];
            atomicOr(&s_mem[idx >> 5], 1u << (idx & 31));
        }
        __syncthreads();

        if (tid == 0) poll_ge(&g_mask_done, gen + 1u);
        __syncthreads();

        // ---- deduped intersection ----
        int cnt = 0;
        for (int i = tid; i < NBW; i += TPB)
            cnt += __popc(s_mem[i] & g_maskbits[i]);
        #pragma unroll
        for (int o = 16; o; o >>= 1) cnt += __shfl_down_sync(0xffffffffu, cnt, o);
        __syncthreads();
        if (lane == 0) scanbuf[wid] = cnt;
        __syncthreads();
        if (tid == 0) {
            int s = 0;
            #pragma unroll
            for (int i = 0; i < 32; i++) s += scanbuf[i];
            g_inter[b - 1] = s;
            __threadfence();
            atomicAdd(&g_int_done, 1u);             // one of 64
        }
    }

    // ---- xm builders: blocks 0..10 ----
    if (b < 11) {
        if (tid == 0) poll_ge(&g_int_done, (gen + 1u) * 64u);
        __syncthreads();

        if (tid == 0) {
            float best = -1.0f; int bi = 0;
            #pragma unroll
            for (int i = 0; i < N_CACHE; i++) {
                float r = (float)g_inter[i] / (float)TOPK_K;
                if (r > best) { best = r; bi = i; }   // first-max = argmax
            }
            s_use  = (best >= 0.9f) ? 1 : 0;
            s_best = bi;
        }
        __syncthreads();

        if (!s_use) {
            // top-k path: build my 1024-wide chunk of xm
            const int gi = b * TPB + tid;
            if (gi < N_IN) {
                int sel = (g_maskbits[gi >> 5] >> (gi & 31)) & 1;
                g_xm[gi] = sel ? x[gi] : 0.0f;
            }
            __syncthreads();
            if (tid == 0) {
                __threadfence();
                atomicAdd(&g_xm_done, 1u);          // one of 11
            }
        } else if (b == 0) {
            // cache path (cold): block 0 builds the entire xm
            for (int i = tid; i < N_IN; i += TPB) g_xm[i] = 0.0f;
            __syncthreads();
            const int* brow = cached + s_best * TOPK_K;
            for (int k = tid; k < TOPK_K; k += TPB) {
                int idx = brow[k];
                atomicAdd(&g_xm[idx], x[idx]);      // duplicates = multiplicity
            }
            __syncthreads();
            if (tid == 0) {
                __threadfence();
                atomicAdd(&g_xm_done, 11u);         // full release
            }
        }
        // blocks 1..10 on cache path contribute nothing (block 0 adds all 11)
    }

    // ---- everyone waits for xm, then GEMV ----
    if (tid == 0) poll_ge(&g_xm_done, (gen + 1u) * 11u);
    __syncthreads();

    // ---- GEMV: exact R4 pattern — 1 row/warp, 4096 x 44KB streams ----
    const int row = b * 32 + wid;                // 0..4095
    const float4* __restrict__ w4 = (const float4*)(W + (long long)row * N_IN);
    const float4* __restrict__ x4 = (const float4*)g_xm;

    float a0 = 0.0f, a1 = 0.0f;
    #pragma unroll 4
    for (int it = 0; it < 43; it++) {
        const int j = lane + it * 64;
        float4 w  = __ldcs(w4 + j);
        float4 v  = x4[j];
        a0 += w.x * v.x + w.y * v.y;
        a1 += w.z * v.z + w.w * v.w;
        float4 w2 = __ldcs(w4 + j + 32);
        float4 v2 = x4[j + 32];
        a0 += w2.x * v2.x + w2.y * v2.y;
        a1 += w2.z * v2.z + w2.w * v2.w;
    }
    float acc = a0 + a1;
    #pragma unroll
    for (int o = 16; o; o >>= 1) acc += __shfl_down_sync(0xffffffffu, acc, o);
    if (lane == 0) out[row] = acc + bias[row];
}

// ============================================================================
extern "C" void kernel_launch(void* const* d_in, const int* in_sizes, int n_in,
                              void* d_out, int out_size) {
    const float* x      = (const float*)d_in[0];
    const float* W      = (const float*)d_in[1];
    const float* bias   = (const float*)d_in[2];
    const int*   cached = (const int*)d_in[3];
    float*       out    = (float*)d_out;

    mega_kernel<<<GRID, TPB>>>(x, cached, W, bias, out);
}